// round 13
// baseline (speedup 1.0000x reference)
#include <cuda_runtime.h>
#include <cuda_fp16.h>
#include <cstdint>

// DistMult forward scoring:
//   score[e] = sum_d h[src[e],d] * fwd_rel[etype[e],d] * h[dst[e],d]
// E = 640000, D = 128. Index arrays are int32 on device (JAX x64 disabled).
//
// R13 = R12's src-grouped CSR plan (hu loaded once per node into registers:
// h-row L2 traffic 327MB -> ~170MB, attacking the measured ~12.6TB/s LTS
// byte bound) with the preprocessing pipeline rebuilt for cost:
//   k1: fused zero(hist) + fp32->fp16 cvt      (~1.6us)
//   k2: hist via no-return atomicAdd (REDG)    (~2us)
//   k3: scan, all counters loaded upfront      (~2.5us, was 12.5)
//   k4: scatter, records packed to int2        (~3us)
//   k5: main CSR kernel                        (~14.5us)
// Records: ((dst<<10)|etype, eid)  [dst<16384 fits 14b, etype<1024 10b]

#define EMB_DIM   128
#define FULL      0xffffffffu
#define MAX_NODES 16384
#define MAX_RELS  1024
#define MAX_EDGES 1048576

__device__ __half g_h16[MAX_NODES * EMB_DIM];   // 4 MB fp16 h
__device__ __half g_w16[MAX_RELS  * EMB_DIM];   // 256 KB fp16 rel
__device__ int    g_cnt[MAX_NODES + 1];
__device__ int    g_offs[MAX_NODES + 1];
__device__ int    g_cursor[MAX_NODES + 1];
__device__ int2   g_recs[MAX_EDGES];            // (packed dst|etype, eid)

// ---- k1: fused zero + fp32->fp16 conversion ----
// Blocks [0, zb): zero g_cnt. Blocks [zb, ...): convert 16 floats/thread.
__global__ __launch_bounds__(256) void prep_kernel(
    const float* __restrict__ h,
    const float* __restrict__ w,
    int n_nodes, int zb, int n_h16, int n_tot16)
{
    if (blockIdx.x < zb) {
        const int i = blockIdx.x * blockDim.x + threadIdx.x;
        if (i <= n_nodes) g_cnt[i] = 0;
        return;
    }
    const int i = (blockIdx.x - zb) * blockDim.x + threadIdx.x;
    if (i >= n_tot16) return;

    const float4* in;
    uint4* out;
    if (i < n_h16) {
        in  = reinterpret_cast<const float4*>(h) + i * 4;
        out = reinterpret_cast<uint4*>(g_h16) + i * 2;
    } else {
        const int j = i - n_h16;
        in  = reinterpret_cast<const float4*>(w) + j * 4;
        out = reinterpret_cast<uint4*>(g_w16) + j * 2;
    }

    const float4 v0 = __ldcs(in + 0);
    const float4 v1 = __ldcs(in + 1);
    const float4 v2 = __ldcs(in + 2);
    const float4 v3 = __ldcs(in + 3);

    __half2 p0 = __floats2half2_rn(v0.x, v0.y);
    __half2 p1 = __floats2half2_rn(v0.z, v0.w);
    __half2 p2 = __floats2half2_rn(v1.x, v1.y);
    __half2 p3 = __floats2half2_rn(v1.z, v1.w);
    __half2 p4 = __floats2half2_rn(v2.x, v2.y);
    __half2 p5 = __floats2half2_rn(v2.z, v2.w);
    __half2 p6 = __floats2half2_rn(v3.x, v3.y);
    __half2 p7 = __floats2half2_rn(v3.z, v3.w);

    uint4 o0, o1;
    o0.x = *reinterpret_cast<uint32_t*>(&p0);
    o0.y = *reinterpret_cast<uint32_t*>(&p1);
    o0.z = *reinterpret_cast<uint32_t*>(&p2);
    o0.w = *reinterpret_cast<uint32_t*>(&p3);
    o1.x = *reinterpret_cast<uint32_t*>(&p4);
    o1.y = *reinterpret_cast<uint32_t*>(&p5);
    o1.z = *reinterpret_cast<uint32_t*>(&p6);
    o1.w = *reinterpret_cast<uint32_t*>(&p7);
    out[0] = o0;
    out[1] = o1;
}

// ---- k2: histogram of src (no-return atomicAdd -> REDG) ----
__global__ __launch_bounds__(256) void hist_kernel(
    const int* __restrict__ src, int n_edges)
{
    const int i = blockIdx.x * blockDim.x + threadIdx.x;
    if (i < n_edges) atomicAdd(&g_cnt[src[i]], 1);
}

// ---- k3: single-block exclusive scan; counters loaded upfront (MLP=K) ----
template<int K>
__global__ __launch_bounds__(1024) void scan_kernel(int n)
{
    __shared__ int warp_sums[32];
    const int tid  = threadIdx.x;
    const int lane = tid & 31;
    const int wid  = tid >> 5;

    // Load K counters per thread in one burst.
    int v[K];
    const int base = tid * K;
    #pragma unroll
    for (int k = 0; k < K; k++)
        v[k] = (base + k < n) ? g_cnt[base + k] : 0;

    // Local inclusive prefix -> thread total in v[K-1].
    #pragma unroll
    for (int k = 1; k < K; k++) v[k] += v[k - 1];
    const int tot = v[K - 1];

    // Block scan of per-thread totals.
    int x = tot;
    #pragma unroll
    for (int o = 1; o < 32; o <<= 1) {
        int y = __shfl_up_sync(FULL, x, o);
        if (lane >= o) x += y;
    }
    if (lane == 31) warp_sums[wid] = x;
    __syncthreads();
    if (wid == 0) {
        int s = warp_sums[lane];
        #pragma unroll
        for (int o = 1; o < 32; o <<= 1) {
            int y = __shfl_up_sync(FULL, s, o);
            if (lane >= o) s += y;
        }
        warp_sums[lane] = s;
    }
    __syncthreads();

    const int warp_off = (wid == 0) ? 0 : warp_sums[wid - 1];
    int excl = warp_off + x - tot;     // exclusive offset of this thread's run

    #pragma unroll
    for (int k = 0; k < K; k++) {
        const int idx = base + k;
        const int e = excl + ((k == 0) ? 0 : v[k - 1]);
        if (idx < n) { g_offs[idx] = e; g_cursor[idx] = e; }
    }
    if (tid == 1023) g_offs[n] = warp_sums[31];
    else if (base >= n && base - K < n) { /* nothing */ }
    if (tid == 0 && 1024 * K >= n) { /* g_offs[n] written by tid 1023 above */ }
}

// ---- k4: scatter edges into src-grouped packed records ----
__global__ __launch_bounds__(256) void scatter_kernel(
    const int* __restrict__ src,
    const int* __restrict__ dst,
    const int* __restrict__ etype,
    int n_edges)
{
    const int i = blockIdx.x * blockDim.x + threadIdx.x;
    if (i >= n_edges) return;
    const int s = src[i];
    const int p = atomicAdd(&g_cursor[s], 1);
    g_recs[p] = make_int2((dst[i] << 10) | etype[i], i);
}

// acc2 += (u*w) * v over one uint4 triple (8 halves = 4 half2), all fp16x2.
__device__ __forceinline__ __half2 fma8_h2(uint4 u, uint4 w, uint4 v, __half2 acc2)
{
    const uint32_t* pu = reinterpret_cast<const uint32_t*>(&u);
    const uint32_t* pw = reinterpret_cast<const uint32_t*>(&w);
    const uint32_t* pv = reinterpret_cast<const uint32_t*>(&v);
    #pragma unroll
    for (int k = 0; k < 4; k++) {
        __half2 hu = *reinterpret_cast<const __half2*>(pu + k);
        __half2 hw = *reinterpret_cast<const __half2*>(pw + k);
        __half2 hv = *reinterpret_cast<const __half2*>(pv + k);
        acc2 = __hfma2(__hmul2(hu, hw), hv, acc2);
    }
    return acc2;
}

// ---- k5: main. 2 warps per src node; hu cached in registers ----
__global__ __launch_bounds__(256) void distmult_csr_kernel(
    float* __restrict__ out, int n_nodes)
{
    const int gwarp = (blockIdx.x * blockDim.x + threadIdx.x) >> 5;
    const int node  = gwarp >> 1;       // 2 warps per node
    const int sub   = gwarp & 1;
    if (node >= n_nodes) return;

    const int lane  = threadIdx.x & 31;
    const int group = lane >> 3;        // 0..3 : record within the quad
    const int sl    = lane & 7;         // 0..7 : sub-lane within a record

    const int beg = g_offs[node];
    const int end = g_offs[node + 1];
    if (beg + sub * 4 >= end) return;   // uniform per warp

    // h[src] row: loaded once, reused for all this node's edges.
    const uint4* __restrict__ RU =
        reinterpret_cast<const uint4*>(g_h16 + (size_t)node * EMB_DIM);
    const uint4 u0 = __ldg(RU + sl);
    const uint4 u1 = __ldg(RU + sl + 8);

    for (int b = beg + sub * 4; b < end; b += 8) {
        const int ridx   = b + group;
        const bool valid = (ridx < end);
        const int2 r = g_recs[valid ? ridx : (end - 1)];
        const int dn = r.x >> 10;           // dst node
        const int et = r.x & 1023;          // etype

        const uint4* __restrict__ RV =
            reinterpret_cast<const uint4*>(g_h16 + (size_t)dn * EMB_DIM);
        const uint4* __restrict__ RW =
            reinterpret_cast<const uint4*>(g_w16 + (size_t)et * EMB_DIM);

        const uint4 av0 = __ldcg(RV + sl);       // h[dst]: L2 stream
        const uint4 av1 = __ldcg(RV + sl + 8);
        const uint4 aw0 = __ldg (RW + sl);       // rel: L1-resident
        const uint4 aw1 = __ldg (RW + sl + 8);

        __half2 z = __float2half2_rn(0.0f);
        __half2 acc2a = fma8_h2(u0, aw0, av0, z);
        __half2 acc2b = fma8_h2(u1, aw1, av1, z);

        const float2 fa = __half22float2(acc2a);
        const float2 fb = __half22float2(acc2b);
        float acc = (fa.x + fa.y) + (fb.x + fb.y);

        acc += __shfl_xor_sync(FULL, acc, 4);
        acc += __shfl_xor_sync(FULL, acc, 2);
        acc += __shfl_xor_sync(FULL, acc, 1);

        if (valid && sl == 0) out[r.y] = acc;
    }
}

// ---- fp32 fallback for unexpected dimensions ----
__global__ __launch_bounds__(256, 8) void distmult_fp32_kernel(
    const float* __restrict__ h,
    const int* __restrict__ src,
    const int* __restrict__ dst,
    const int* __restrict__ etype,
    const float* __restrict__ fwd_rel,
    float* __restrict__ out,
    int n_edges)
{
    const int warp  = (blockIdx.x * blockDim.x + threadIdx.x) >> 5;
    const int lane  = threadIdx.x & 31;
    const int group = lane >> 3;
    const int sl    = lane & 7;

    int e = warp * 4 + group;
    const bool valid = (e < n_edges);
    if (warp * 4 >= n_edges) return;
    const int ec = valid ? e : (n_edges - 1);

    const int s = src[ec];
    const int d = dst[ec];
    const int t = etype[ec];

    const float4* __restrict__ hu = reinterpret_cast<const float4*>(h + (size_t)s * EMB_DIM);
    const float4* __restrict__ hv = reinterpret_cast<const float4*>(h + (size_t)d * EMB_DIM);
    const float4* __restrict__ wr = reinterpret_cast<const float4*>(fwd_rel + (size_t)t * EMB_DIM);

    float acc = 0.0f;
    #pragma unroll
    for (int j = 0; j < 4; j++) {
        const int idx = sl + j * 8;
        const float4 a = __ldcg(hu + idx);
        const float4 c = __ldcg(hv + idx);
        const float4 b = __ldg(wr + idx);
        float p = a.x * b.x * c.x;
        p = fmaf(a.y * b.y, c.y, p);
        p = fmaf(a.z * b.z, c.z, p);
        p = fmaf(a.w * b.w, c.w, p);
        acc += p;
    }
    acc += __shfl_xor_sync(FULL, acc, 4);
    acc += __shfl_xor_sync(FULL, acc, 2);
    acc += __shfl_xor_sync(FULL, acc, 1);
    if (valid && sl == 0) out[e] = acc;
}

extern "C" void kernel_launch(void* const* d_in, const int* in_sizes, int n_in,
                              void* d_out, int out_size)
{
    const float* h       = (const float*)d_in[0];
    const int*   src     = (const int*)d_in[1];
    const int*   dst     = (const int*)d_in[2];
    const int*   etype   = (const int*)d_in[3];
    const float* fwd_rel = (const float*)d_in[4];
    // d_in[5] = rev_rel, unused in forward scoring.
    float* out = (float*)d_out;

    const int n_edges = in_sizes[1];
    const int h_elems = in_sizes[0];
    const int w_elems = in_sizes[4];
    const int n_nodes = h_elems / EMB_DIM;
    const int n_rels  = w_elems / EMB_DIM;

    // Scan template handles up to 1024*16 nodes.
    if (h_elems % EMB_DIM != 0 || n_nodes > MAX_NODES ||
        n_rels > MAX_RELS || (w_elems & 15) || (h_elems & 15) ||
        n_edges > MAX_EDGES) {
        const int blocks = (n_edges + 31) / 32;
        distmult_fp32_kernel<<<blocks, 256>>>(h, src, dst, etype, fwd_rel,
                                              out, n_edges);
        return;
    }

    const int n_h16   = h_elems / 16;
    const int n_tot16 = n_h16 + w_elems / 16;
    const int zb      = (n_nodes + 256) / 256;       // zero blocks
    const int cb      = (n_tot16 + 255) / 256;       // cvt blocks
    const int eb      = (n_edges + 255) / 256;

    prep_kernel<<<zb + cb, 256>>>(h, fwd_rel, n_nodes, zb, n_h16, n_tot16);
    hist_kernel<<<eb, 256>>>(src, n_edges);
    scan_kernel<16><<<1, 1024>>>(n_nodes);
    scatter_kernel<<<eb, 256>>>(src, dst, etype, n_edges);

    const int warps  = 2 * n_nodes;                  // 2 warps per node
    const int blocks = (warps + 7) / 8;
    distmult_csr_kernel<<<blocks, 256>>>(out, n_nodes);
}

// round 14
// speedup vs baseline: 2.3841x; 2.3841x over previous
#include <cuda_runtime.h>
#include <cuda_fp16.h>
#include <cstdint>

// DistMult forward scoring:
//   score[e] = sum_d h[src[e],d] * fwd_rel[etype[e],d] * h[dst[e],d]
// E = 640000, D = 128. Index arrays are int32 on device (JAX x64 disabled).
//
// R14 = R11 reverted (proven 27.1us; main kernel sits exactly at the
// measured LTS byte cap: 345MB @ ~12.9TB/s) + faster cvt prologue
// (32 floats/thread, MLP=8: 1.3us -> ~0.8us).
// CSR/grouping abandoned: preprocessing cost (>=10us per replay, atomic
// serialization) ~ equals the hu-reuse savings (~12.5us). Negative EV.
//
// Main kernel: 8 lanes/edge, 4 edges/warp; fp16 rows = 256B.
//   h16 -> __ldcg  (L2-only: h rows have ~0.86 refs/SM -> no L1 value,
//                   and bypassing protects w's L1 residency)
//   w16 -> __ldg   (128KB, L1-resident, ~8.6 refs/row/SM)
// Math: HMUL2+HFMA2 fp16x2 accumulation (4 terms deep per acc), fp32 final.

#define EMB_DIM   128
#define FULL      0xffffffffu
#define MAX_NODES 16384
#define MAX_RELS  1024

__device__ __half g_h16[MAX_NODES * EMB_DIM];   // 4 MB scratch
__device__ __half g_w16[MAX_RELS  * EMB_DIM];   // 256 KB scratch

// ---- merged fp32 -> fp16 conversion, 32 floats (4 uint4 out) per thread ----
__global__ __launch_bounds__(256) void cvt_merged_kernel(
    const float* __restrict__ h,
    const float* __restrict__ w,
    int n_h32, int n_tot32)
{
    const int i = blockIdx.x * blockDim.x + threadIdx.x;
    if (i >= n_tot32) return;

    const float4* in;
    uint4* out;
    if (i < n_h32) {
        in  = reinterpret_cast<const float4*>(h) + i * 8;
        out = reinterpret_cast<uint4*>(g_h16) + i * 4;
    } else {
        const int j = i - n_h32;
        in  = reinterpret_cast<const float4*>(w) + j * 8;
        out = reinterpret_cast<uint4*>(g_w16) + j * 4;
    }

    // 8 independent streaming loads (MLP=8).
    float4 v[8];
    #pragma unroll
    for (int k = 0; k < 8; k++) v[k] = __ldcs(in + k);

    #pragma unroll
    for (int k = 0; k < 4; k++) {
        __half2 p0 = __floats2half2_rn(v[2*k].x,   v[2*k].y);
        __half2 p1 = __floats2half2_rn(v[2*k].z,   v[2*k].w);
        __half2 p2 = __floats2half2_rn(v[2*k+1].x, v[2*k+1].y);
        __half2 p3 = __floats2half2_rn(v[2*k+1].z, v[2*k+1].w);
        uint4 o;
        o.x = *reinterpret_cast<uint32_t*>(&p0);
        o.y = *reinterpret_cast<uint32_t*>(&p1);
        o.z = *reinterpret_cast<uint32_t*>(&p2);
        o.w = *reinterpret_cast<uint32_t*>(&p3);
        out[k] = o;
    }
}

// acc2 += (u*w) * v over one uint4 triple (8 halves = 4 half2), all fp16x2.
__device__ __forceinline__ __half2 fma8_h2(uint4 u, uint4 w, uint4 v, __half2 acc2)
{
    const uint32_t* pu = reinterpret_cast<const uint32_t*>(&u);
    const uint32_t* pw = reinterpret_cast<const uint32_t*>(&w);
    const uint32_t* pv = reinterpret_cast<const uint32_t*>(&v);
    #pragma unroll
    for (int k = 0; k < 4; k++) {
        __half2 hu = *reinterpret_cast<const __half2*>(pu + k);
        __half2 hw = *reinterpret_cast<const __half2*>(pw + k);
        __half2 hv = *reinterpret_cast<const __half2*>(pv + k);
        acc2 = __hfma2(__hmul2(hu, hw), hv, acc2);   // 2 instrs per half2
    }
    return acc2;
}

__global__ __launch_bounds__(256, 7) void distmult_fp16_kernel(
    const int* __restrict__ src,
    const int* __restrict__ dst,
    const int* __restrict__ etype,
    float* __restrict__ out,
    int n_edges)
{
    const int warp  = (blockIdx.x * blockDim.x + threadIdx.x) >> 5;
    const int lane  = threadIdx.x & 31;
    const int group = lane >> 3;   // 0..3 : edge within the quad
    const int sl    = lane & 7;    // 0..7 : sub-lane within the edge

    int e = warp * 4 + group;
    const bool valid = (e < n_edges);
    if (warp * 4 >= n_edges) return;
    const int ec = valid ? e : (n_edges - 1);

    const int s = src[ec];
    const int d = dst[ec];
    const int t = etype[ec];

    const uint4* __restrict__ RU =
        reinterpret_cast<const uint4*>(g_h16 + (size_t)s * EMB_DIM);
    const uint4* __restrict__ RV =
        reinterpret_cast<const uint4*>(g_h16 + (size_t)d * EMB_DIM);
    const uint4* __restrict__ RW =
        reinterpret_cast<const uint4*>(g_w16 + (size_t)t * EMB_DIM);

    // Two independent fp16x2 accumulators: each element sums only 4 terms,
    // keeping fp16 accumulation error small; combined once in fp32 below.
    const uint4 au0 = __ldcg(RU + sl);        // h: L2-only
    const uint4 av0 = __ldcg(RV + sl);
    const uint4 aw0 = __ldg (RW + sl);        // rel: L1-resident
    const uint4 au1 = __ldcg(RU + sl + 8);
    const uint4 av1 = __ldcg(RV + sl + 8);
    const uint4 aw1 = __ldg (RW + sl + 8);

    __half2 z = __float2half2_rn(0.0f);
    __half2 acc2a = fma8_h2(au0, aw0, av0, z);
    __half2 acc2b = fma8_h2(au1, aw1, av1, z);

    const float2 fa = __half22float2(acc2a);
    const float2 fb = __half22float2(acc2b);
    float acc = (fa.x + fa.y) + (fb.x + fb.y);

    // Reduce across the 8 sub-lanes of each group.
    acc += __shfl_xor_sync(FULL, acc, 4);
    acc += __shfl_xor_sync(FULL, acc, 2);
    acc += __shfl_xor_sync(FULL, acc, 1);

    if (valid && sl == 0) out[e] = acc;     // 4 contiguous floats / warp
}

// ---- fp32 fallback (R6 kernel) for unexpected dimensions ----
__global__ __launch_bounds__(256, 8) void distmult_fp32_kernel(
    const float* __restrict__ h,
    const int* __restrict__ src,
    const int* __restrict__ dst,
    const int* __restrict__ etype,
    const float* __restrict__ fwd_rel,
    float* __restrict__ out,
    int n_edges)
{
    const int warp  = (blockIdx.x * blockDim.x + threadIdx.x) >> 5;
    const int lane  = threadIdx.x & 31;
    const int group = lane >> 3;
    const int sl    = lane & 7;

    int e = warp * 4 + group;
    const bool valid = (e < n_edges);
    if (warp * 4 >= n_edges) return;
    const int ec = valid ? e : (n_edges - 1);

    const int s = src[ec];
    const int d = dst[ec];
    const int t = etype[ec];

    const float4* __restrict__ hu = reinterpret_cast<const float4*>(h + (size_t)s * EMB_DIM);
    const float4* __restrict__ hv = reinterpret_cast<const float4*>(h + (size_t)d * EMB_DIM);
    const float4* __restrict__ wr = reinterpret_cast<const float4*>(fwd_rel + (size_t)t * EMB_DIM);

    float acc = 0.0f;
    #pragma unroll
    for (int j = 0; j < 4; j++) {
        const int idx = sl + j * 8;
        const float4 a = __ldcg(hu + idx);
        const float4 c = __ldcg(hv + idx);
        const float4 b = __ldg(wr + idx);
        float p = a.x * b.x * c.x;
        p = fmaf(a.y * b.y, c.y, p);
        p = fmaf(a.z * b.z, c.z, p);
        p = fmaf(a.w * b.w, c.w, p);
        acc += p;
    }
    acc += __shfl_xor_sync(FULL, acc, 4);
    acc += __shfl_xor_sync(FULL, acc, 2);
    acc += __shfl_xor_sync(FULL, acc, 1);
    if (valid && sl == 0) out[e] = acc;
}

extern "C" void kernel_launch(void* const* d_in, const int* in_sizes, int n_in,
                              void* d_out, int out_size)
{
    const float* h       = (const float*)d_in[0];
    const int*   src     = (const int*)d_in[1];
    const int*   dst     = (const int*)d_in[2];
    const int*   etype   = (const int*)d_in[3];
    const float* fwd_rel = (const float*)d_in[4];
    // d_in[5] = rev_rel, unused in forward scoring.
    float* out = (float*)d_out;

    const int n_edges = in_sizes[1];   // src element count
    const int h_elems = in_sizes[0];   // n_nodes * 128
    const int w_elems = in_sizes[4];   // num_rels * 128

    const int threads = 256;
    const int blocks  = (n_edges + 31) / 32;   // 8 warps x 4 edges per block

    if (h_elems > MAX_NODES * EMB_DIM || w_elems > MAX_RELS * EMB_DIM ||
        (h_elems & 31) || (w_elems & 31)) {
        // Unexpected dims: proven fp32 path.
        distmult_fp32_kernel<<<blocks, threads>>>(h, src, dst, etype, fwd_rel,
                                                  out, n_edges);
        return;
    }

    // Prologue: merged fp32 -> fp16 staging (one launch, 32 floats/thread).
    const int n_h32   = h_elems / 32;
    const int n_tot32 = n_h32 + w_elems / 32;
    cvt_merged_kernel<<<(n_tot32 + 255) / 256, 256>>>(h, fwd_rel, n_h32, n_tot32);

    distmult_fp16_kernel<<<blocks, threads>>>(src, dst, etype, out, n_edges);
}

// round 15
// speedup vs baseline: 2.5898x; 1.0863x over previous
#include <cuda_runtime.h>
#include <cuda_fp16.h>
#include <cstdint>

// DistMult forward scoring:
//   score[e] = sum_d h[src[e],d] * fwd_rel[etype[e],d] * h[dst[e],d]
// E = 640000, D = 128. Index arrays are int32 on device (JAX x64 disabled).
//
// R15 = R11 restored (best measured: 27.1us). The main kernel runs at the
// chip-wide LTS byte cap (~345MB @ ~12.9TB/s); R12-R14 established that all
// further byte-cut avenues are negative-EV (CSR preprocessing >= savings;
// fp8 fails 1e-3; smem-w shrinks the L1 carveout below usefulness).
// The cvt prologue uses 16 floats/thread (329 blocks) — the 32-float variant
// halves the grid to ~1 block/SM and costs +2.3us (R14 regression).
//
// Main kernel: 8 lanes/edge, 4 edges/warp; fp16 rows = 256B.
//   h16 -> __ldcg  (L2-only: ~0.86 h-row refs/SM -> no L1 value; protects w)
//   w16 -> __ldg   (128KB, L1-resident, ~8.6 refs/row/SM)
// Math: HMUL2+HFMA2 fp16x2 accumulation (4 terms deep per element), fp32
// final combine + 3-shuffle reduction.

#define EMB_DIM   128
#define FULL      0xffffffffu
#define MAX_NODES 16384
#define MAX_RELS  1024

__device__ __half g_h16[MAX_NODES * EMB_DIM];   // 4 MB scratch
__device__ __half g_w16[MAX_RELS  * EMB_DIM];   // 256 KB scratch

// ---- merged fp32 -> fp16 conversion, 16 floats (2 uint4 out) per thread ----
__global__ __launch_bounds__(256) void cvt_merged_kernel(
    const float* __restrict__ h,
    const float* __restrict__ w,
    int n_h16, int n_tot16)
{
    const int i = blockIdx.x * blockDim.x + threadIdx.x;
    if (i >= n_tot16) return;

    const float4* in;
    uint4* out;
    if (i < n_h16) {
        in  = reinterpret_cast<const float4*>(h) + i * 4;
        out = reinterpret_cast<uint4*>(g_h16) + i * 2;
    } else {
        const int j = i - n_h16;
        in  = reinterpret_cast<const float4*>(w) + j * 4;
        out = reinterpret_cast<uint4*>(g_w16) + j * 2;
    }

    // 4 independent streaming loads (MLP=4).
    const float4 v0 = __ldcs(in + 0);
    const float4 v1 = __ldcs(in + 1);
    const float4 v2 = __ldcs(in + 2);
    const float4 v3 = __ldcs(in + 3);

    __half2 p0 = __floats2half2_rn(v0.x, v0.y);
    __half2 p1 = __floats2half2_rn(v0.z, v0.w);
    __half2 p2 = __floats2half2_rn(v1.x, v1.y);
    __half2 p3 = __floats2half2_rn(v1.z, v1.w);
    __half2 p4 = __floats2half2_rn(v2.x, v2.y);
    __half2 p5 = __floats2half2_rn(v2.z, v2.w);
    __half2 p6 = __floats2half2_rn(v3.x, v3.y);
    __half2 p7 = __floats2half2_rn(v3.z, v3.w);

    uint4 o0, o1;
    o0.x = *reinterpret_cast<uint32_t*>(&p0);
    o0.y = *reinterpret_cast<uint32_t*>(&p1);
    o0.z = *reinterpret_cast<uint32_t*>(&p2);
    o0.w = *reinterpret_cast<uint32_t*>(&p3);
    o1.x = *reinterpret_cast<uint32_t*>(&p4);
    o1.y = *reinterpret_cast<uint32_t*>(&p5);
    o1.z = *reinterpret_cast<uint32_t*>(&p6);
    o1.w = *reinterpret_cast<uint32_t*>(&p7);
    out[0] = o0;
    out[1] = o1;
}

// acc2 += (u*w) * v over one uint4 triple (8 halves = 4 half2), all fp16x2.
__device__ __forceinline__ __half2 fma8_h2(uint4 u, uint4 w, uint4 v, __half2 acc2)
{
    const uint32_t* pu = reinterpret_cast<const uint32_t*>(&u);
    const uint32_t* pw = reinterpret_cast<const uint32_t*>(&w);
    const uint32_t* pv = reinterpret_cast<const uint32_t*>(&v);
    #pragma unroll
    for (int k = 0; k < 4; k++) {
        __half2 hu = *reinterpret_cast<const __half2*>(pu + k);
        __half2 hw = *reinterpret_cast<const __half2*>(pw + k);
        __half2 hv = *reinterpret_cast<const __half2*>(pv + k);
        acc2 = __hfma2(__hmul2(hu, hw), hv, acc2);   // 2 instrs per half2
    }
    return acc2;
}

__global__ __launch_bounds__(256, 7) void distmult_fp16_kernel(
    const int* __restrict__ src,
    const int* __restrict__ dst,
    const int* __restrict__ etype,
    float* __restrict__ out,
    int n_edges)
{
    const int warp  = (blockIdx.x * blockDim.x + threadIdx.x) >> 5;
    const int lane  = threadIdx.x & 31;
    const int group = lane >> 3;   // 0..3 : edge within the quad
    const int sl    = lane & 7;    // 0..7 : sub-lane within the edge

    int e = warp * 4 + group;
    const bool valid = (e < n_edges);
    if (warp * 4 >= n_edges) return;
    const int ec = valid ? e : (n_edges - 1);

    const int s = src[ec];
    const int d = dst[ec];
    const int t = etype[ec];

    const uint4* __restrict__ RU =
        reinterpret_cast<const uint4*>(g_h16 + (size_t)s * EMB_DIM);
    const uint4* __restrict__ RV =
        reinterpret_cast<const uint4*>(g_h16 + (size_t)d * EMB_DIM);
    const uint4* __restrict__ RW =
        reinterpret_cast<const uint4*>(g_w16 + (size_t)t * EMB_DIM);

    // Two independent fp16x2 accumulators: each element sums only 4 terms,
    // keeping fp16 accumulation error small; combined once in fp32 below.
    const uint4 au0 = __ldcg(RU + sl);        // h: L2-only
    const uint4 av0 = __ldcg(RV + sl);
    const uint4 aw0 = __ldg (RW + sl);        // rel: L1-resident
    const uint4 au1 = __ldcg(RU + sl + 8);
    const uint4 av1 = __ldcg(RV + sl + 8);
    const uint4 aw1 = __ldg (RW + sl + 8);

    __half2 z = __float2half2_rn(0.0f);
    __half2 acc2a = fma8_h2(au0, aw0, av0, z);
    __half2 acc2b = fma8_h2(au1, aw1, av1, z);

    const float2 fa = __half22float2(acc2a);
    const float2 fb = __half22float2(acc2b);
    float acc = (fa.x + fa.y) + (fb.x + fb.y);

    // Reduce across the 8 sub-lanes of each group.
    acc += __shfl_xor_sync(FULL, acc, 4);
    acc += __shfl_xor_sync(FULL, acc, 2);
    acc += __shfl_xor_sync(FULL, acc, 1);

    if (valid && sl == 0) out[e] = acc;     // 4 contiguous floats / warp
}

// ---- fp32 fallback (R6 kernel) for unexpected dimensions ----
__global__ __launch_bounds__(256, 8) void distmult_fp32_kernel(
    const float* __restrict__ h,
    const int* __restrict__ src,
    const int* __restrict__ dst,
    const int* __restrict__ etype,
    const float* __restrict__ fwd_rel,
    float* __restrict__ out,
    int n_edges)
{
    const int warp  = (blockIdx.x * blockDim.x + threadIdx.x) >> 5;
    const int lane  = threadIdx.x & 31;
    const int group = lane >> 3;
    const int sl    = lane & 7;

    int e = warp * 4 + group;
    const bool valid = (e < n_edges);
    if (warp * 4 >= n_edges) return;
    const int ec = valid ? e : (n_edges - 1);

    const int s = src[ec];
    const int d = dst[ec];
    const int t = etype[ec];

    const float4* __restrict__ hu = reinterpret_cast<const float4*>(h + (size_t)s * EMB_DIM);
    const float4* __restrict__ hv = reinterpret_cast<const float4*>(h + (size_t)d * EMB_DIM);
    const float4* __restrict__ wr = reinterpret_cast<const float4*>(fwd_rel + (size_t)t * EMB_DIM);

    float acc = 0.0f;
    #pragma unroll
    for (int j = 0; j < 4; j++) {
        const int idx = sl + j * 8;
        const float4 a = __ldcg(hu + idx);
        const float4 c = __ldcg(hv + idx);
        const float4 b = __ldg(wr + idx);
        float p = a.x * b.x * c.x;
        p = fmaf(a.y * b.y, c.y, p);
        p = fmaf(a.z * b.z, c.z, p);
        p = fmaf(a.w * b.w, c.w, p);
        acc += p;
    }
    acc += __shfl_xor_sync(FULL, acc, 4);
    acc += __shfl_xor_sync(FULL, acc, 2);
    acc += __shfl_xor_sync(FULL, acc, 1);
    if (valid && sl == 0) out[e] = acc;
}

extern "C" void kernel_launch(void* const* d_in, const int* in_sizes, int n_in,
                              void* d_out, int out_size)
{
    const float* h       = (const float*)d_in[0];
    const int*   src     = (const int*)d_in[1];
    const int*   dst     = (const int*)d_in[2];
    const int*   etype   = (const int*)d_in[3];
    const float* fwd_rel = (const float*)d_in[4];
    // d_in[5] = rev_rel, unused in forward scoring.
    float* out = (float*)d_out;

    const int n_edges = in_sizes[1];   // src element count
    const int h_elems = in_sizes[0];   // n_nodes * 128
    const int w_elems = in_sizes[4];   // num_rels * 128

    const int threads = 256;
    const int blocks  = (n_edges + 31) / 32;   // 8 warps x 4 edges per block

    if (h_elems > MAX_NODES * EMB_DIM || w_elems > MAX_RELS * EMB_DIM ||
        (h_elems & 15) || (w_elems & 15)) {
        // Unexpected dims: proven fp32 path.
        distmult_fp32_kernel<<<blocks, threads>>>(h, src, dst, etype, fwd_rel,
                                                  out, n_edges);
        return;
    }

    // Prologue: merged fp32 -> fp16 staging (one launch, 16 floats/thread).
    const int n_h16   = h_elems / 16;
    const int n_tot16 = n_h16 + w_elems / 16;
    cvt_merged_kernel<<<(n_tot16 + 255) / 256, 256>>>(h, fwd_rel, n_h16, n_tot16);

    distmult_fp16_kernel<<<blocks, threads>>>(src, dst, etype, out, n_edges);
}